// round 15
// baseline (speedup 1.0000x reference)
#include <cuda_runtime.h>
#include <cuda_fp16.h>
#include <math.h>
#include <float.h>
#include <stdint.h>

// Problem constants
#define BATCH   4
#define TSEQ    1024
#define DMODEL  1024
#define NHEAD   16
#define HDIM    64
#define NLAYER  4
#define VOCAB   32000
#define NTOK    (BATCH*TSEQ)        // 4096 rows
#define FFDIM   (4*DMODEL)          // 4096

// ---------------- scratch (device globals; no allocation allowed) ----------
__device__ float  g_h   [(size_t)NTOK*DMODEL];
__device__ __half g_xn16[(size_t)NTOK*DMODEL];
__device__ __half g_q16 [(size_t)NTOK*DMODEL];
__device__ __half g_k16 [(size_t)NTOK*DMODEL];
__device__ __half g_v16 [(size_t)NTOK*DMODEL];
__device__ __half g_ff16[(size_t)NTOK*FFDIM];
__device__ __half g_wqkv[(size_t)3*DMODEL*DMODEL];   // [3072, 1024] K-major
__device__ float  g_bqkv[3*DMODEL];
__device__ __half g_w1t [(size_t)FFDIM*DMODEL];      // [4096, 1024]
__device__ __half g_w2t [(size_t)DMODEL*FFDIM];      // [1024, 4096]
__device__ __half g_woT [(size_t)VOCAB*DMODEL];      // [32000, 1024]

// ======================= PTX helpers ========================================
__device__ __forceinline__ uint32_t smem_u32(const void* p) {
    uint32_t a;
    asm("{ .reg .u64 t; cvta.to.shared.u64 t, %1; cvt.u32.u64 %0, t; }"
        : "=r"(a) : "l"(p));
    return a;
}
__device__ __forceinline__ uint32_t h2u(__half2 h) {
    union { __half2 h; uint32_t u; } cvt;
    cvt.h = h;
    return cvt.u;
}
__device__ __forceinline__ void cpa16(uint32_t dst, const void* src) {
    asm volatile("cp.async.cg.shared.global [%0], [%1], 16;" :: "r"(dst), "l"(src));
}
#define CP_COMMIT() asm volatile("cp.async.commit_group;" ::: "memory")
#define CP_WAIT(n)  asm volatile("cp.async.wait_group %0;" :: "n"(n) : "memory")

__device__ __forceinline__ void ldsm4(uint32_t* r, uint32_t a) {
    asm volatile("ldmatrix.sync.aligned.m8n8.x4.shared.b16 {%0,%1,%2,%3}, [%4];"
        : "=r"(r[0]), "=r"(r[1]), "=r"(r[2]), "=r"(r[3]) : "r"(a));
}
__device__ __forceinline__ void ldsm2(uint32_t* r, uint32_t a) {
    asm volatile("ldmatrix.sync.aligned.m8n8.x2.shared.b16 {%0,%1}, [%2];"
        : "=r"(r[0]), "=r"(r[1]) : "r"(a));
}
__device__ __forceinline__ void ldsm2t(uint32_t* r, uint32_t a) {
    asm volatile("ldmatrix.sync.aligned.m8n8.x2.trans.shared.b16 {%0,%1}, [%2];"
        : "=r"(r[0]), "=r"(r[1]) : "r"(a));
}
__device__ __forceinline__ void mma16816(float* c, const uint32_t* a, const uint32_t* b) {
    asm volatile("mma.sync.aligned.m16n8k16.row.col.f32.f16.f16.f32 "
        "{%0,%1,%2,%3}, {%4,%5,%6,%7}, {%8,%9}, {%0,%1,%2,%3};"
        : "+f"(c[0]), "+f"(c[1]), "+f"(c[2]), "+f"(c[3])
        : "r"(a[0]), "r"(a[1]), "r"(a[2]), "r"(a[3]), "r"(b[0]), "r"(b[1]));
}

// ======================= HMMA GEMM (128x128x32, 4-stage) ====================
// C[M,N] = A[M,K](fp16 row-major) @ B[N,K](fp16 K-major)^T + bias
// 4-stage cp.async pipeline, loads issued BEFORE compute (3 stages of cover).
// 81,920 B dynamic smem/CTA: 2 CTAs/SM (160 KB < 228 KB) preserved.
// MODE 0: fp32 out (Cf)   MODE 1: relu -> fp16 (Ch)
// MODE 2: fp32 += (residual into Cf)
// MODE 3: QKV split -> fp16 Ch/Chk/Chv (N-chunks of 1024)
#define BM 128
#define BN 128
#define BK 32
#define ASTR 80                       // bytes per 32-half row (64B data + 16B pad)
#define A_BYTES (BM * ASTR)           // 10240
#define STG ((BM + BN) * ASTR)        // 20480
#define NSTG 4
#define GEMM_SMEM (NSTG * STG)        // 81920

template<int MODE>
__global__ __launch_bounds__(256)
void tgemm(const __half* __restrict__ A, const __half* __restrict__ B,
           const float* __restrict__ bias,
           float* Cf, __half* Ch, __half* Chk, __half* Chv,
           int N, int K) {
    extern __shared__ __align__(16) char dsm[];
    const int tid = threadIdx.x;
    const int w = tid >> 5, lane = tid & 31;
    const int wm = w & 1, wn = w >> 1;
    const int bm = blockIdx.x * BM, bn = blockIdx.y * BN;

    const __half* Ab = A + (size_t)bm * K;
    const __half* Bb = B + (size_t)bn * K;
    const int row_l = tid >> 2, ch_l = tid & 3;

    auto load_stage = [&](int s, int st) {
        char* bA = dsm + st * STG;
        char* bB = bA + A_BYTES;
        const __half* As = Ab + s * BK;
        const __half* Bs = Bb + s * BK;
        #pragma unroll
        for (int i = 0; i < 2; i++) {
            int r = row_l + i * 64;
            cpa16(smem_u32(bA + r * ASTR + ch_l * 16), As + (size_t)r * K + ch_l * 8);
            cpa16(smem_u32(bB + r * ASTR + ch_l * 16), Bs + (size_t)r * K + ch_l * 8);
        }
    };

    float acc[4][4][4] = {};
    const int S = K / BK;

    load_stage(0, 0); CP_COMMIT();
    load_stage(1, 1); CP_COMMIT();
    load_stage(2, 2); CP_COMMIT();

    int st = 0;                       // slot of stage s
    for (int s = 0; s < S; s++) {
        if (s < S - 2)      { CP_WAIT(2); }
        else if (s < S - 1) { CP_WAIT(1); }
        else                { CP_WAIT(0); }
        __syncthreads();              // stage s ready; slot (s+3)%4 free
        if (s + 3 < S) {
            int st3 = st + 3; if (st3 >= NSTG) st3 -= NSTG;
            load_stage(s + 3, st3);
            CP_COMMIT();
        }
        uint32_t ab = smem_u32(dsm + st * STG);
        uint32_t bb = ab + A_BYTES;
        #pragma unroll
        for (int ks = 0; ks < 2; ks++) {
            uint32_t af[4][4], bf[4][2];
            #pragma unroll
            for (int mi = 0; mi < 4; mi++) {
                int r = wm * 64 + mi * 16 + (lane & 15);
                ldsm4(af[mi], ab + r * ASTR + ks * 32 + ((lane >> 4) << 4));
            }
            #pragma unroll
            for (int nj = 0; nj < 4; nj++) {
                int r = wn * 32 + nj * 8 + (lane & 7);
                ldsm2(bf[nj], bb + r * ASTR + ks * 32 + (((lane >> 3) & 1) << 4));
            }
            #pragma unroll
            for (int mi = 0; mi < 4; mi++)
                #pragma unroll
                for (int nj = 0; nj < 4; nj++)
                    mma16816(acc[mi][nj], af[mi], bf[nj]);
        }
        if (++st == NSTG) st = 0;
    }

    const int l4 = lane >> 2, l2 = (lane & 3) * 2;
    #pragma unroll
    for (int mi = 0; mi < 4; mi++) {
        int m0 = bm + wm * 64 + mi * 16 + l4;
        #pragma unroll
        for (int nj = 0; nj < 4; nj++) {
            int ng = bn + wn * 32 + nj * 8 + l2;
            float b0 = bias[ng], b1 = bias[ng + 1];
            float v00 = acc[mi][nj][0] + b0, v01 = acc[mi][nj][1] + b1;
            float v10 = acc[mi][nj][2] + b0, v11 = acc[mi][nj][3] + b1;
            if (MODE == 3) {
                int which = bn >> 10;
                __half* dst = (which == 0) ? Ch : (which == 1) ? Chk : Chv;
                int nc = ng & 1023;
                *(__half2*)(dst + (size_t)m0 * DMODEL + nc)       = __floats2half2_rn(v00, v01);
                *(__half2*)(dst + (size_t)(m0 + 8) * DMODEL + nc) = __floats2half2_rn(v10, v11);
            } else if (MODE == 1) {
                *(__half2*)(Ch + (size_t)m0 * N + ng) =
                    __floats2half2_rn(fmaxf(v00, 0.f), fmaxf(v01, 0.f));
                *(__half2*)(Ch + (size_t)(m0 + 8) * N + ng) =
                    __floats2half2_rn(fmaxf(v10, 0.f), fmaxf(v11, 0.f));
            } else {
                float* p0 = Cf + (size_t)m0 * N + ng;
                float* p1 = Cf + (size_t)(m0 + 8) * N + ng;
                if (MODE == 2) {
                    float2 o0 = *(float2*)p0, o1 = *(float2*)p1;
                    v00 += o0.x; v01 += o0.y; v10 += o1.x; v11 += o1.y;
                }
                *(float2*)p0 = make_float2(v00, v01);
                *(float2*)p1 = make_float2(v10, v11);
            }
        }
    }
}

// ======================= fused flash attention + O projection ==============
// (R10 configuration: 64 Q-rows/block, 128 threads — best measured.)
// Double-buffered cp.async K/V prefetch. Exact source-quirk mask: scale,
// then (s>t || val==0) -> -inf. Online softmax in fp32. Epilogue: O_norm
// (fp16 A-frags) @ Wo[h] (fp16 in reused sQ smem), + bias, += into H.
#define FSTR 144   // 64 halves (128B) + 16B pad per row

__global__ __launch_bounds__(128)
void fattn_kernel(const __half* __restrict__ Q, const __half* __restrict__ K,
                  const __half* __restrict__ V,
                  const float* __restrict__ Wo, const float* __restrict__ bo,
                  float* __restrict__ H) {
    __shared__ __align__(16) char sQ[64 * FSTR];
    __shared__ __align__(16) char sK[2][64 * FSTR];
    __shared__ __align__(16) char sV[2][64 * FSTR];
    const int t0 = blockIdx.x * 64;
    const int bh = blockIdx.y, b = bh >> 4, h = bh & 15;
    const int tid = threadIdx.x, w = tid >> 5, lane = tid & 31;
    const int l4 = lane >> 2, l2 = (lane & 3) * 2;
    const size_t base = (size_t)b * TSEQ * DMODEL + h * HDIM;

    // load Q tile (64 x 64 halfs), direct stores
    #pragma unroll
    for (int i = 0; i < 4; i++) {
        int idx = tid + i * 128;
        int r = idx >> 3, cseg = idx & 7;
        *(uint4*)(sQ + r * FSTR + cseg * 16) =
            *(const uint4*)(Q + base + (size_t)(t0 + r) * DMODEL + cseg * 8);
    }

    auto load_kv = [&](int s0, int buf) {
        #pragma unroll
        for (int i = 0; i < 4; i++) {
            int idx = tid + i * 128;
            int r = idx >> 3, cseg = idx & 7;
            cpa16(smem_u32(&sK[buf][r * FSTR + cseg * 16]),
                  K + base + (size_t)(s0 + r) * DMODEL + cseg * 8);
            cpa16(smem_u32(&sV[buf][r * FSTR + cseg * 16]),
                  V + base + (size_t)(s0 + r) * DMODEL + cseg * 8);
        }
    };

    // prefetch KV block 0
    load_kv(0, 0);
    CP_COMMIT();
    __syncthreads();            // sQ visible to all

    uint32_t sqb = smem_u32(sQ);
    uint32_t qf[4][4];
    #pragma unroll
    for (int ks = 0; ks < 4; ks++)
        ldsm4(qf[ks], sqb + (w * 16 + (lane & 15)) * FSTR + ks * 32
                       + ((lane >> 4) << 4));
    __syncthreads();            // all warps done reading sQ

    // repurpose sQ: Wo[h] as fp16 [v][n] 64x64 (row stride FSTR)
    {
        const float* woh = Wo + (size_t)h * (HDIM * HDIM);
        #pragma unroll
        for (int i = 0; i < 8; i++) {
            int idx = tid + i * 128;               // 0..1023
            int r = idx >> 4, c4 = (idx & 15) * 4;
            float4 v = *(const float4*)(woh + r * HDIM + c4);
            *(__half2*)(sQ + r * FSTR + c4 * 2)     = __floats2half2_rn(v.x, v.y);
            *(__half2*)(sQ + r * FSTR + c4 * 2 + 4) = __floats2half2_rn(v.z, v.w);
        }
    }

    float m_run[2] = {-FLT_MAX, -FLT_MAX};
    float l_run[2] = {0.f, 0.f};
    float o[8][4] = {};
    const int tg0 = t0 + w * 16 + l4;      // rows (within batch) this thread owns
    const int tg1 = tg0 + 8;
    const int nblk = t0 / 64 + 1;

    for (int ib = 0; ib < nblk; ib++) {
        const int s0 = ib * 64;
        const int buf = ib & 1;
        if (ib + 1 < nblk) load_kv(s0 + 64, buf ^ 1);
        CP_COMMIT();
        if (ib + 1 < nblk) { CP_WAIT(1); } else { CP_WAIT(0); }
        __syncthreads();        // KV[buf] (and, on iter 0, sQ=Wo) visible

        uint32_t skb = smem_u32(&sK[buf][0]);
        uint32_t svb = smem_u32(&sV[buf][0]);

        // ---- S = Q K^T (fp32 accum) ----
        float sc[8][4] = {};
        #pragma unroll
        for (int ks = 0; ks < 4; ks++) {
            #pragma unroll
            for (int nj = 0; nj < 8; nj++) {
                uint32_t bf[2];
                ldsm2(bf, skb + (nj * 8 + (lane & 7)) * FSTR + ks * 32
                           + (((lane >> 3) & 1) << 4));
                mma16816(sc[nj], qf[ks], bf);
            }
        }
        // ---- scale + mask (source quirk) ----
        float rmax0 = -FLT_MAX, rmax1 = -FLT_MAX;
        #pragma unroll
        for (int nj = 0; nj < 8; nj++) {
            int sg = s0 + nj * 8 + l2;
            #pragma unroll
            for (int q = 0; q < 2; q++) {
                float v0 = sc[nj][q] * 0.125f;
                float v2 = sc[nj][q + 2] * 0.125f;
                if (sg + q > tg0 || v0 == 0.f) v0 = -FLT_MAX;
                if (sg + q > tg1 || v2 == 0.f) v2 = -FLT_MAX;
                sc[nj][q] = v0; sc[nj][q + 2] = v2;
                rmax0 = fmaxf(rmax0, v0); rmax1 = fmaxf(rmax1, v2);
            }
        }
        rmax0 = fmaxf(rmax0, __shfl_xor_sync(0xFFFFFFFFu, rmax0, 1));
        rmax0 = fmaxf(rmax0, __shfl_xor_sync(0xFFFFFFFFu, rmax0, 2));
        rmax1 = fmaxf(rmax1, __shfl_xor_sync(0xFFFFFFFFu, rmax1, 1));
        rmax1 = fmaxf(rmax1, __shfl_xor_sync(0xFFFFFFFFu, rmax1, 2));
        float nm0 = fmaxf(m_run[0], rmax0), nm1 = fmaxf(m_run[1], rmax1);
        float al0 = __expf(m_run[0] - nm0), al1 = __expf(m_run[1] - nm1);
        m_run[0] = nm0; m_run[1] = nm1;
        float rs0 = 0.f, rs1 = 0.f;
        #pragma unroll
        for (int nj = 0; nj < 8; nj++) {
            #pragma unroll
            for (int q = 0; q < 2; q++) {
                float p0 = (sc[nj][q]     == -FLT_MAX) ? 0.f : __expf(sc[nj][q]     - nm0);
                float p2 = (sc[nj][q + 2] == -FLT_MAX) ? 0.f : __expf(sc[nj][q + 2] - nm1);
                sc[nj][q] = p0; sc[nj][q + 2] = p2;
                rs0 += p0; rs1 += p2;
            }
        }
        rs0 += __shfl_xor_sync(0xFFFFFFFFu, rs0, 1);
        rs0 += __shfl_xor_sync(0xFFFFFFFFu, rs0, 2);
        rs1 += __shfl_xor_sync(0xFFFFFFFFu, rs1, 1);
        rs1 += __shfl_xor_sync(0xFFFFFFFFu, rs1, 2);
        l_run[0] = l_run[0] * al0 + rs0;
        l_run[1] = l_run[1] * al1 + rs1;
        #pragma unroll
        for (int nj = 0; nj < 8; nj++) {
            o[nj][0] *= al0; o[nj][1] *= al0;
            o[nj][2] *= al1; o[nj][3] *= al1;
        }
        // ---- O += P V ----
        #pragma unroll
        for (int kv = 0; kv < 4; kv++) {
            uint32_t pa[4];
            pa[0] = h2u(__floats2half2_rn(sc[2*kv][0],   sc[2*kv][1]));
            pa[1] = h2u(__floats2half2_rn(sc[2*kv][2],   sc[2*kv][3]));
            pa[2] = h2u(__floats2half2_rn(sc[2*kv+1][0], sc[2*kv+1][1]));
            pa[3] = h2u(__floats2half2_rn(sc[2*kv+1][2], sc[2*kv+1][3]));
            #pragma unroll
            for (int nj = 0; nj < 8; nj++) {
                uint32_t bf[2];
                ldsm2t(bf, svb + (kv * 16 + (lane & 15)) * FSTR + nj * 16);
                mma16816(o[nj], pa, bf);
            }
        }
        __syncthreads();        // protect KV[buf] before next prefetch reuses it
    }

    // ---- fused O projection: (O * inv_l) @ Wo[h] + bo[h], += into H ----
    float inv0 = 1.f / l_run[0], inv1 = 1.f / l_run[1];
    float oa[8][4] = {};
    uint32_t swo = smem_u32(sQ);
    #pragma unroll
    for (int kv = 0; kv < 4; kv++) {
        uint32_t pa[4];
        pa[0] = h2u(__floats2half2_rn(o[2*kv][0]   * inv0, o[2*kv][1]   * inv0));
        pa[1] = h2u(__floats2half2_rn(o[2*kv][2]   * inv1, o[2*kv][3]   * inv1));
        pa[2] = h2u(__floats2half2_rn(o[2*kv+1][0] * inv0, o[2*kv+1][1] * inv0));
        pa[3] = h2u(__floats2half2_rn(o[2*kv+1][2] * inv1, o[2*kv+1][3] * inv1));
        #pragma unroll
        for (int nj = 0; nj < 8; nj++) {
            uint32_t bf[2];
            ldsm2t(bf, swo + (kv * 16 + (lane & 15)) * FSTR + nj * 16);
            mma16816(oa[nj], pa, bf);
        }
    }
    const float* boh = bo + h * HDIM;
    float* hp0 = H + (size_t)(b * TSEQ + tg0) * DMODEL + h * HDIM;
    float* hp1 = H + (size_t)(b * TSEQ + tg1) * DMODEL + h * HDIM;
    #pragma unroll
    for (int nj = 0; nj < 8; nj++) {
        int c = nj * 8 + l2;
        float b0 = boh[c], b1 = boh[c + 1];
        float2 r0 = *(float2*)(hp0 + c);
        float2 r1 = *(float2*)(hp1 + c);
        *(float2*)(hp0 + c) = make_float2(r0.x + oa[nj][0] + b0,
                                          r0.y + oa[nj][1] + b1);
        *(float2*)(hp1 + c) = make_float2(r1.x + oa[nj][2] + b0,
                                          r1.y + oa[nj][3] + b1);
    }
}

// ======================= misc kernels ======================================
template<bool DOMAX>
__device__ __forceinline__ float block_reduce(float x) {
    #pragma unroll
    for (int o = 16; o; o >>= 1) {
        float t = __shfl_xor_sync(0xFFFFFFFFu, x, o);
        x = DOMAX ? fmaxf(x, t) : x + t;
    }
    __shared__ float sh[8];
    int w = threadIdx.x >> 5;
    __syncthreads();
    if ((threadIdx.x & 31) == 0) sh[w] = x;
    __syncthreads();
    float r = sh[0];
    #pragma unroll
    for (int i = 1; i < 8; i++) r = DOMAX ? fmaxf(r, sh[i]) : r + sh[i];
    return r;
}

__global__ __launch_bounds__(256) void embed_kernel(const int* __restrict__ x,
                                                    const float* __restrict__ tok,
                                                    const float* __restrict__ pos,
                                                    float* __restrict__ H) {
    int row = blockIdx.x;
    int tid = row % TSEQ;
    size_t tb = (size_t)x[row] * DMODEL, pb = (size_t)tid * DMODEL;
    size_t hb = (size_t)row * DMODEL;
    #pragma unroll
    for (int i = 0; i < 4; i++) {
        int c = threadIdx.x + i * 256;
        H[hb + c] = tok[tb + c] + pos[pb + c];
    }
}

// layernorm: fp32 in -> fp16 out (float4 I/O)
__global__ __launch_bounds__(256) void ln_kernel(const float* __restrict__ X,
                                                 const float* __restrict__ g,
                                                 const float* __restrict__ b,
                                                 __half* __restrict__ O) {
    size_t base = (size_t)blockIdx.x * DMODEL;
    int c = threadIdx.x * 4;
    float4 v = *(const float4*)&X[base + c];
    float s = v.x + v.y + v.z + v.w;
    float sq = v.x*v.x + v.y*v.y + v.z*v.z + v.w*v.w;
    s  = block_reduce<false>(s);
    sq = block_reduce<false>(sq);
    float mu = s * (1.f / DMODEL);
    float rstd = rsqrtf(sq * (1.f / DMODEL) - mu * mu + 1e-5f);
    float4 gv = *(const float4*)&g[c];
    float4 bv = *(const float4*)&b[c];
    __half2 h0 = __floats2half2_rn((v.x - mu) * rstd * gv.x + bv.x,
                                   (v.y - mu) * rstd * gv.y + bv.y);
    __half2 h1 = __floats2half2_rn((v.z - mu) * rstd * gv.z + bv.z,
                                   (v.w - mu) * rstd * gv.w + bv.w);
    *(__half2*)&O[base + c]     = h0;
    *(__half2*)&O[base + c + 2] = h1;
}

__global__ void transpose16(const float* __restrict__ S, __half* __restrict__ D,
                            int R, int C) {
    __shared__ float t[32][33];
    int c0 = blockIdx.x * 32, r0 = blockIdx.y * 32;
    #pragma unroll
    for (int i = 0; i < 4; i++)
        t[threadIdx.y + i*8][threadIdx.x] =
            S[(size_t)(r0 + threadIdx.y + i*8) * C + c0 + threadIdx.x];
    __syncthreads();
    #pragma unroll
    for (int i = 0; i < 4; i++)
        D[(size_t)(c0 + threadIdx.y + i*8) * R + r0 + threadIdx.x] =
            __float2half(t[threadIdx.x][threadIdx.y + i*8]);
}

__global__ void repack_headT(const float* __restrict__ W, __half* __restrict__ D) {
    __shared__ float t[32][33];
    int h = blockIdx.z;
    int k0 = blockIdx.x * 32, d0 = blockIdx.y * 32;
    #pragma unroll
    for (int i = 0; i < 4; i++)
        t[threadIdx.y + i*8][threadIdx.x] =
            W[((size_t)(h*DMODEL + d0 + threadIdx.y + i*8)) * HDIM + k0 + threadIdx.x];
    __syncthreads();
    #pragma unroll
    for (int i = 0; i < 4; i++)
        D[((size_t)(h*HDIM + k0 + threadIdx.y + i*8)) * DMODEL + d0 + threadIdx.x] =
            __float2half(t[threadIdx.x][threadIdx.y + i*8]);
}

__global__ void catbias(const float* a, const float* b, const float* c, float* o) {
    int i = blockIdx.x * 256 + threadIdx.x;
    o[i] = (i < 1024) ? a[i] : (i < 2048) ? b[i - 1024] : c[i - 2048];
}

// ---------------- driver ----------------------------------------------------
extern "C" void kernel_launch(void* const* d_in, const int* in_sizes, int n_in,
                              void* d_out, int out_size) {
    const int*   x    = (const int*)  d_in[0];
    const float* tok  = (const float*)d_in[1];
    const float* pos  = (const float*)d_in[2];
    const float* Wq   = (const float*)d_in[3];
    const float* bq   = (const float*)d_in[4];
    const float* Wk   = (const float*)d_in[5];
    const float* bk   = (const float*)d_in[6];
    const float* Wv   = (const float*)d_in[7];
    const float* bv   = (const float*)d_in[8];
    const float* Wo   = (const float*)d_in[9];
    const float* bo   = (const float*)d_in[10];
    const float* W1   = (const float*)d_in[11];
    const float* b1   = (const float*)d_in[12];
    const float* W2   = (const float*)d_in[13];
    const float* b2   = (const float*)d_in[14];
    const float* ln1g = (const float*)d_in[15];
    const float* ln1b = (const float*)d_in[16];
    const float* ln2g = (const float*)d_in[17];
    const float* ln2b = (const float*)d_in[18];
    const float* lnfg = (const float*)d_in[19];
    const float* lnfb = (const float*)d_in[20];
    const float* Wout = (const float*)d_in[21];
    const float* bout = (const float*)d_in[22];
    float* out = (float*)d_out;

    float *ph, *pbqkv;
    __half *pxn, *pff, *pq, *pk, *pv, *pwqkv, *pw1t, *pw2t, *pwoT;
    cudaGetSymbolAddress((void**)&ph,    g_h);
    cudaGetSymbolAddress((void**)&pxn,   g_xn16);
    cudaGetSymbolAddress((void**)&pq,    g_q16);
    cudaGetSymbolAddress((void**)&pk,    g_k16);
    cudaGetSymbolAddress((void**)&pv,    g_v16);
    cudaGetSymbolAddress((void**)&pff,   g_ff16);
    cudaGetSymbolAddress((void**)&pwqkv, g_wqkv);
    cudaGetSymbolAddress((void**)&pbqkv, g_bqkv);
    cudaGetSymbolAddress((void**)&pw1t,  g_w1t);
    cudaGetSymbolAddress((void**)&pw2t,  g_w2t);
    cudaGetSymbolAddress((void**)&pwoT,  g_woT);

    cudaFuncSetAttribute(tgemm<0>, cudaFuncAttributeMaxDynamicSharedMemorySize, GEMM_SMEM);
    cudaFuncSetAttribute(tgemm<1>, cudaFuncAttributeMaxDynamicSharedMemorySize, GEMM_SMEM);
    cudaFuncSetAttribute(tgemm<2>, cudaFuncAttributeMaxDynamicSharedMemorySize, GEMM_SMEM);
    cudaFuncSetAttribute(tgemm<3>, cudaFuncAttributeMaxDynamicSharedMemorySize, GEMM_SMEM);

    dim3 tb(32, 8);
    repack_headT<<<dim3(2, 32, 16), tb>>>(Wq, pwqkv);
    repack_headT<<<dim3(2, 32, 16), tb>>>(Wk, pwqkv + (size_t)DMODEL*DMODEL);
    repack_headT<<<dim3(2, 32, 16), tb>>>(Wv, pwqkv + (size_t)2*DMODEL*DMODEL);
    catbias<<<12, 256>>>(bq, bk, bv, pbqkv);
    transpose16<<<dim3(FFDIM/32, DMODEL/32), tb>>>(W1, pw1t, DMODEL, FFDIM);
    transpose16<<<dim3(DMODEL/32, FFDIM/32), tb>>>(W2, pw2t, FFDIM, DMODEL);
    transpose16<<<dim3(VOCAB/32, DMODEL/32), tb>>>(Wout, pwoT, DMODEL, VOCAB);

    embed_kernel<<<NTOK, 256>>>(x, tok, pos, ph);

    for (int layer = 0; layer < NLAYER; layer++) {
        ln_kernel<<<NTOK, 256>>>(ph, ln1g, ln1b, pxn);
        tgemm<3><<<dim3(NTOK/BM, 3*DMODEL/BN), 256, GEMM_SMEM>>>(
            pxn, pwqkv, pbqkv, nullptr, pq, pk, pv, 3*DMODEL, DMODEL);

        fattn_kernel<<<dim3(TSEQ/64, BATCH*NHEAD), 128>>>(pq, pk, pv, Wo, bo, ph);

        ln_kernel<<<NTOK, 256>>>(ph, ln2g, ln2b, pxn);
        tgemm<1><<<dim3(NTOK/BM, FFDIM/BN), 256, GEMM_SMEM>>>(
            pxn, pw1t, b1, nullptr, pff, nullptr, nullptr, FFDIM, DMODEL);
        tgemm<2><<<dim3(NTOK/BM, DMODEL/BN), 256, GEMM_SMEM>>>(
            pff, pw2t, b2, ph, nullptr, nullptr, nullptr, DMODEL, FFDIM);
    }

    ln_kernel<<<NTOK, 256>>>(ph, lnfg, lnfb, pxn);
    tgemm<0><<<dim3(NTOK/BM, VOCAB/BN), 256, GEMM_SMEM>>>(
        pxn, pwoT, bout, out, nullptr, nullptr, nullptr, VOCAB, DMODEL);
}

// round 16
// speedup vs baseline: 1.0198x; 1.0198x over previous
#include <cuda_runtime.h>
#include <cuda_fp16.h>
#include <math.h>
#include <float.h>
#include <stdint.h>

// Problem constants
#define BATCH   4
#define TSEQ    1024
#define DMODEL  1024
#define NHEAD   16
#define HDIM    64
#define NLAYER  4
#define VOCAB   32000
#define NTOK    (BATCH*TSEQ)        // 4096 rows
#define FFDIM   (4*DMODEL)          // 4096

// ---------------- scratch (device globals; no allocation allowed) ----------
__device__ float  g_h   [(size_t)NTOK*DMODEL];
__device__ __half g_xn16[(size_t)NTOK*DMODEL];
__device__ __half g_q16 [(size_t)NTOK*DMODEL];
__device__ __half g_k16 [(size_t)NTOK*DMODEL];
__device__ __half g_v16 [(size_t)NTOK*DMODEL];
__device__ __half g_ff16[(size_t)NTOK*FFDIM];
__device__ __half g_wqkv[(size_t)3*DMODEL*DMODEL];   // [3072, 1024] K-major
__device__ float  g_bqkv[3*DMODEL];
__device__ __half g_w1t [(size_t)FFDIM*DMODEL];      // [4096, 1024]
__device__ __half g_w2t [(size_t)DMODEL*FFDIM];      // [1024, 4096]
__device__ __half g_woT [(size_t)VOCAB*DMODEL];      // [32000, 1024]

// ======================= PTX helpers ========================================
__device__ __forceinline__ uint32_t smem_u32(const void* p) {
    uint32_t a;
    asm("{ .reg .u64 t; cvta.to.shared.u64 t, %1; cvt.u32.u64 %0, t; }"
        : "=r"(a) : "l"(p));
    return a;
}
__device__ __forceinline__ uint32_t h2u(__half2 h) {
    union { __half2 h; uint32_t u; } cvt;
    cvt.h = h;
    return cvt.u;
}
__device__ __forceinline__ void cpa16(uint32_t dst, const void* src) {
    asm volatile("cp.async.cg.shared.global [%0], [%1], 16;" :: "r"(dst), "l"(src));
}
#define CP_COMMIT() asm volatile("cp.async.commit_group;" ::: "memory")
#define CP_WAIT(n)  asm volatile("cp.async.wait_group %0;" :: "n"(n) : "memory")

__device__ __forceinline__ void ldsm4(uint32_t* r, uint32_t a) {
    asm volatile("ldmatrix.sync.aligned.m8n8.x4.shared.b16 {%0,%1,%2,%3}, [%4];"
        : "=r"(r[0]), "=r"(r[1]), "=r"(r[2]), "=r"(r[3]) : "r"(a));
}
__device__ __forceinline__ void ldsm2(uint32_t* r, uint32_t a) {
    asm volatile("ldmatrix.sync.aligned.m8n8.x2.shared.b16 {%0,%1}, [%2];"
        : "=r"(r[0]), "=r"(r[1]) : "r"(a));
}
__device__ __forceinline__ void ldsm2t(uint32_t* r, uint32_t a) {
    asm volatile("ldmatrix.sync.aligned.m8n8.x2.trans.shared.b16 {%0,%1}, [%2];"
        : "=r"(r[0]), "=r"(r[1]) : "r"(a));
}
__device__ __forceinline__ void mma16816(float* c, const uint32_t* a, const uint32_t* b) {
    asm volatile("mma.sync.aligned.m16n8k16.row.col.f32.f16.f16.f32 "
        "{%0,%1,%2,%3}, {%4,%5,%6,%7}, {%8,%9}, {%0,%1,%2,%3};"
        : "+f"(c[0]), "+f"(c[1]), "+f"(c[2]), "+f"(c[3])
        : "r"(a[0]), "r"(a[1]), "r"(a[2]), "r"(a[3]), "r"(b[0]), "r"(b[1]));
}

// ======================= HMMA GEMM (128x128x32, 3-stage) ====================
// C[M,N] = A[M,K](fp16 row-major) @ B[N,K](fp16 K-major)^T + bias
// 3-stage cp.async pipeline, loads issued BEFORE compute (2 stages of cover).
// B fragments loaded pairwise via ldmatrix.x4 (half the LDSM issue count).
// MODE 0: fp32 out (Cf)   MODE 1: relu -> fp16 (Ch)
// MODE 2: fp32 += (residual into Cf)
// MODE 3: QKV split -> fp16 Ch/Chk/Chv (N-chunks of 1024)
#define BM 128
#define BN 128
#define BK 32
#define ASTR 80                       // bytes per 32-half row (64B data + 16B pad)
#define A_BYTES (BM * ASTR)           // 10240
#define STG ((BM + BN) * ASTR)        // 20480
#define GEMM_SMEM (3 * STG)           // 61440

template<int MODE>
__global__ __launch_bounds__(256)
void tgemm(const __half* __restrict__ A, const __half* __restrict__ B,
           const float* __restrict__ bias,
           float* Cf, __half* Ch, __half* Chk, __half* Chv,
           int N, int K) {
    extern __shared__ __align__(16) char dsm[];
    const int tid = threadIdx.x;
    const int w = tid >> 5, lane = tid & 31;
    const int wm = w & 1, wn = w >> 1;
    const int bm = blockIdx.x * BM, bn = blockIdx.y * BN;

    const __half* Ab = A + (size_t)bm * K;
    const __half* Bb = B + (size_t)bn * K;
    const int row_l = tid >> 2, ch_l = tid & 3;

    auto load_stage = [&](int s, int st) {
        char* bA = dsm + st * STG;
        char* bB = bA + A_BYTES;
        const __half* As = Ab + s * BK;
        const __half* Bs = Bb + s * BK;
        #pragma unroll
        for (int i = 0; i < 2; i++) {
            int r = row_l + i * 64;
            cpa16(smem_u32(bA + r * ASTR + ch_l * 16), As + (size_t)r * K + ch_l * 8);
            cpa16(smem_u32(bB + r * ASTR + ch_l * 16), Bs + (size_t)r * K + ch_l * 8);
        }
    };

    float acc[4][4][4] = {};
    const int S = K / BK;

    load_stage(0, 0); CP_COMMIT();
    load_stage(1, 1); CP_COMMIT();

    int st = 0;                       // slot of stage s
    for (int s = 0; s < S; s++) {
        if (s < S - 1) { CP_WAIT(1); } else { CP_WAIT(0); }
        __syncthreads();              // stage s ready; slot (s+2)%3 free
        if (s + 2 < S) {
            int st2 = st + 2; if (st2 >= 3) st2 -= 3;
            load_stage(s + 2, st2);
            CP_COMMIT();
        }
        uint32_t ab = smem_u32(dsm + st * STG);
        uint32_t bb = ab + A_BYTES;
        #pragma unroll
        for (int ks = 0; ks < 2; ks++) {
            uint32_t af[4][4], bf[4][2];
            #pragma unroll
            for (int mi = 0; mi < 4; mi++) {
                int r = wm * 64 + mi * 16 + (lane & 15);
                ldsm4(af[mi], ab + r * ASTR + ks * 32 + ((lane >> 4) << 4));
            }
            // B fragments pairwise: one x4 covers nj and nj+1 (2 matrices x 2 k-halves)
            #pragma unroll
            for (int njp = 0; njp < 2; njp++) {
                uint32_t r4[4];
                int r = wn * 32 + (njp * 2 + (lane >> 4)) * 8 + (lane & 7);
                ldsm4(r4, bb + r * ASTR + ks * 32 + (((lane >> 3) & 1) << 4));
                bf[njp*2][0]   = r4[0]; bf[njp*2][1]   = r4[1];
                bf[njp*2+1][0] = r4[2]; bf[njp*2+1][1] = r4[3];
            }
            #pragma unroll
            for (int mi = 0; mi < 4; mi++)
                #pragma unroll
                for (int nj = 0; nj < 4; nj++)
                    mma16816(acc[mi][nj], af[mi], bf[nj]);
        }
        if (++st == 3) st = 0;
    }

    const int l4 = lane >> 2, l2 = (lane & 3) * 2;
    #pragma unroll
    for (int mi = 0; mi < 4; mi++) {
        int m0 = bm + wm * 64 + mi * 16 + l4;
        #pragma unroll
        for (int nj = 0; nj < 4; nj++) {
            int ng = bn + wn * 32 + nj * 8 + l2;
            float b0 = bias[ng], b1 = bias[ng + 1];
            float v00 = acc[mi][nj][0] + b0, v01 = acc[mi][nj][1] + b1;
            float v10 = acc[mi][nj][2] + b0, v11 = acc[mi][nj][3] + b1;
            if (MODE == 3) {
                int which = bn >> 10;
                __half* dst = (which == 0) ? Ch : (which == 1) ? Chk : Chv;
                int nc = ng & 1023;
                *(__half2*)(dst + (size_t)m0 * DMODEL + nc)       = __floats2half2_rn(v00, v01);
                *(__half2*)(dst + (size_t)(m0 + 8) * DMODEL + nc) = __floats2half2_rn(v10, v11);
            } else if (MODE == 1) {
                *(__half2*)(Ch + (size_t)m0 * N + ng) =
                    __floats2half2_rn(fmaxf(v00, 0.f), fmaxf(v01, 0.f));
                *(__half2*)(Ch + (size_t)(m0 + 8) * N + ng) =
                    __floats2half2_rn(fmaxf(v10, 0.f), fmaxf(v11, 0.f));
            } else {
                float* p0 = Cf + (size_t)m0 * N + ng;
                float* p1 = Cf + (size_t)(m0 + 8) * N + ng;
                if (MODE == 2) {
                    float2 o0 = *(float2*)p0, o1 = *(float2*)p1;
                    v00 += o0.x; v01 += o0.y; v10 += o1.x; v11 += o1.y;
                }
                *(float2*)p0 = make_float2(v00, v01);
                *(float2*)p1 = make_float2(v10, v11);
            }
        }
    }
}

// ======================= fused flash attention + O projection ==============
// (64 Q-rows/block, 128 threads — best measured.) Double-buffered cp.async
// K/V prefetch; K fragments loaded pairwise via ldmatrix.x4. Exact source
// quirk mask: scale, then (s>t || val==0) -> -inf. Online softmax in fp32.
// Epilogue: O_norm (fp16 A-frags) @ Wo[h] (fp16 in reused sQ smem), + bias,
// += into H.
#define FSTR 144   // 64 halves (128B) + 16B pad per row

__global__ __launch_bounds__(128)
void fattn_kernel(const __half* __restrict__ Q, const __half* __restrict__ K,
                  const __half* __restrict__ V,
                  const float* __restrict__ Wo, const float* __restrict__ bo,
                  float* __restrict__ H) {
    __shared__ __align__(16) char sQ[64 * FSTR];
    __shared__ __align__(16) char sK[2][64 * FSTR];
    __shared__ __align__(16) char sV[2][64 * FSTR];
    const int t0 = blockIdx.x * 64;
    const int bh = blockIdx.y, b = bh >> 4, h = bh & 15;
    const int tid = threadIdx.x, w = tid >> 5, lane = tid & 31;
    const int l4 = lane >> 2, l2 = (lane & 3) * 2;
    const size_t base = (size_t)b * TSEQ * DMODEL + h * HDIM;

    // load Q tile (64 x 64 halfs), direct stores
    #pragma unroll
    for (int i = 0; i < 4; i++) {
        int idx = tid + i * 128;
        int r = idx >> 3, cseg = idx & 7;
        *(uint4*)(sQ + r * FSTR + cseg * 16) =
            *(const uint4*)(Q + base + (size_t)(t0 + r) * DMODEL + cseg * 8);
    }

    auto load_kv = [&](int s0, int buf) {
        #pragma unroll
        for (int i = 0; i < 4; i++) {
            int idx = tid + i * 128;
            int r = idx >> 3, cseg = idx & 7;
            cpa16(smem_u32(&sK[buf][r * FSTR + cseg * 16]),
                  K + base + (size_t)(s0 + r) * DMODEL + cseg * 8);
            cpa16(smem_u32(&sV[buf][r * FSTR + cseg * 16]),
                  V + base + (size_t)(s0 + r) * DMODEL + cseg * 8);
        }
    };

    // prefetch KV block 0
    load_kv(0, 0);
    CP_COMMIT();
    __syncthreads();            // sQ visible to all

    uint32_t sqb = smem_u32(sQ);
    uint32_t qf[4][4];
    #pragma unroll
    for (int ks = 0; ks < 4; ks++)
        ldsm4(qf[ks], sqb + (w * 16 + (lane & 15)) * FSTR + ks * 32
                       + ((lane >> 4) << 4));
    __syncthreads();            // all warps done reading sQ

    // repurpose sQ: Wo[h] as fp16 [v][n] 64x64 (row stride FSTR)
    {
        const float* woh = Wo + (size_t)h * (HDIM * HDIM);
        #pragma unroll
        for (int i = 0; i < 8; i++) {
            int idx = tid + i * 128;               // 0..1023
            int r = idx >> 4, c4 = (idx & 15) * 4;
            float4 v = *(const float4*)(woh + r * HDIM + c4);
            *(__half2*)(sQ + r * FSTR + c4 * 2)     = __floats2half2_rn(v.x, v.y);
            *(__half2*)(sQ + r * FSTR + c4 * 2 + 4) = __floats2half2_rn(v.z, v.w);
        }
    }

    float m_run[2] = {-FLT_MAX, -FLT_MAX};
    float l_run[2] = {0.f, 0.f};
    float o[8][4] = {};
    const int tg0 = t0 + w * 16 + l4;      // rows (within batch) this thread owns
    const int tg1 = tg0 + 8;
    const int nblk = t0 / 64 + 1;

    for (int ib = 0; ib < nblk; ib++) {
        const int s0 = ib * 64;
        const int buf = ib & 1;
        if (ib + 1 < nblk) load_kv(s0 + 64, buf ^ 1);
        CP_COMMIT();
        if (ib + 1 < nblk) { CP_WAIT(1); } else { CP_WAIT(0); }
        __syncthreads();        // KV[buf] (and, on iter 0, sQ=Wo) visible

        uint32_t skb = smem_u32(&sK[buf][0]);
        uint32_t svb = smem_u32(&sV[buf][0]);

        // ---- S = Q K^T (fp32 accum), K fragments pairwise via x4 ----
        float sc[8][4] = {};
        #pragma unroll
        for (int ks = 0; ks < 4; ks++) {
            uint32_t bfk[8][2];
            #pragma unroll
            for (int njp = 0; njp < 4; njp++) {
                uint32_t r4[4];
                int r = (njp * 2 + (lane >> 4)) * 8 + (lane & 7);
                ldsm4(r4, skb + r * FSTR + ks * 32 + (((lane >> 3) & 1) << 4));
                bfk[njp*2][0]   = r4[0]; bfk[njp*2][1]   = r4[1];
                bfk[njp*2+1][0] = r4[2]; bfk[njp*2+1][1] = r4[3];
            }
            #pragma unroll
            for (int nj = 0; nj < 8; nj++)
                mma16816(sc[nj], qf[ks], bfk[nj]);
        }
        // ---- scale + mask (source quirk) ----
        float rmax0 = -FLT_MAX, rmax1 = -FLT_MAX;
        #pragma unroll
        for (int nj = 0; nj < 8; nj++) {
            int sg = s0 + nj * 8 + l2;
            #pragma unroll
            for (int q = 0; q < 2; q++) {
                float v0 = sc[nj][q] * 0.125f;
                float v2 = sc[nj][q + 2] * 0.125f;
                if (sg + q > tg0 || v0 == 0.f) v0 = -FLT_MAX;
                if (sg + q > tg1 || v2 == 0.f) v2 = -FLT_MAX;
                sc[nj][q] = v0; sc[nj][q + 2] = v2;
                rmax0 = fmaxf(rmax0, v0); rmax1 = fmaxf(rmax1, v2);
            }
        }
        rmax0 = fmaxf(rmax0, __shfl_xor_sync(0xFFFFFFFFu, rmax0, 1));
        rmax0 = fmaxf(rmax0, __shfl_xor_sync(0xFFFFFFFFu, rmax0, 2));
        rmax1 = fmaxf(rmax1, __shfl_xor_sync(0xFFFFFFFFu, rmax1, 1));
        rmax1 = fmaxf(rmax1, __shfl_xor_sync(0xFFFFFFFFu, rmax1, 2));
        float nm0 = fmaxf(m_run[0], rmax0), nm1 = fmaxf(m_run[1], rmax1);
        float al0 = __expf(m_run[0] - nm0), al1 = __expf(m_run[1] - nm1);
        m_run[0] = nm0; m_run[1] = nm1;
        float rs0 = 0.f, rs1 = 0.f;
        #pragma unroll
        for (int nj = 0; nj < 8; nj++) {
            #pragma unroll
            for (int q = 0; q < 2; q++) {
                float p0 = (sc[nj][q]     == -FLT_MAX) ? 0.f : __expf(sc[nj][q]     - nm0);
                float p2 = (sc[nj][q + 2] == -FLT_MAX) ? 0.f : __expf(sc[nj][q + 2] - nm1);
                sc[nj][q] = p0; sc[nj][q + 2] = p2;
                rs0 += p0; rs1 += p2;
            }
        }
        rs0 += __shfl_xor_sync(0xFFFFFFFFu, rs0, 1);
        rs0 += __shfl_xor_sync(0xFFFFFFFFu, rs0, 2);
        rs1 += __shfl_xor_sync(0xFFFFFFFFu, rs1, 1);
        rs1 += __shfl_xor_sync(0xFFFFFFFFu, rs1, 2);
        l_run[0] = l_run[0] * al0 + rs0;
        l_run[1] = l_run[1] * al1 + rs1;
        #pragma unroll
        for (int nj = 0; nj < 8; nj++) {
            o[nj][0] *= al0; o[nj][1] *= al0;
            o[nj][2] *= al1; o[nj][3] *= al1;
        }
        // ---- O += P V ----
        #pragma unroll
        for (int kv = 0; kv < 4; kv++) {
            uint32_t pa[4];
            pa[0] = h2u(__floats2half2_rn(sc[2*kv][0],   sc[2*kv][1]));
            pa[1] = h2u(__floats2half2_rn(sc[2*kv][2],   sc[2*kv][3]));
            pa[2] = h2u(__floats2half2_rn(sc[2*kv+1][0], sc[2*kv+1][1]));
            pa[3] = h2u(__floats2half2_rn(sc[2*kv+1][2], sc[2*kv+1][3]));
            #pragma unroll
            for (int nj = 0; nj < 8; nj++) {
                uint32_t bf[2];
                ldsm2t(bf, svb + (kv * 16 + (lane & 15)) * FSTR + nj * 16);
                mma16816(o[nj], pa, bf);
            }
        }
        __syncthreads();        // protect KV[buf] before next prefetch reuses it
    }

    // ---- fused O projection: (O * inv_l) @ Wo[h] + bo[h], += into H ----
    float inv0 = 1.f / l_run[0], inv1 = 1.f / l_run[1];
    float oa[8][4] = {};
    uint32_t swo = smem_u32(sQ);
    #pragma unroll
    for (int kv = 0; kv < 4; kv++) {
        uint32_t pa[4];
        pa[0] = h2u(__floats2half2_rn(o[2*kv][0]   * inv0, o[2*kv][1]   * inv0));
        pa[1] = h2u(__floats2half2_rn(o[2*kv][2]   * inv1, o[2*kv][3]   * inv1));
        pa[2] = h2u(__floats2half2_rn(o[2*kv+1][0] * inv0, o[2*kv+1][1] * inv0));
        pa[3] = h2u(__floats2half2_rn(o[2*kv+1][2] * inv1, o[2*kv+1][3] * inv1));
        #pragma unroll
        for (int nj = 0; nj < 8; nj++) {
            uint32_t bf[2];
            ldsm2t(bf, swo + (kv * 16 + (lane & 15)) * FSTR + nj * 16);
            mma16816(oa[nj], pa, bf);
        }
    }
    const float* boh = bo + h * HDIM;
    float* hp0 = H + (size_t)(b * TSEQ + tg0) * DMODEL + h * HDIM;
    float* hp1 = H + (size_t)(b * TSEQ + tg1) * DMODEL + h * HDIM;
    #pragma unroll
    for (int nj = 0; nj < 8; nj++) {
        int c = nj * 8 + l2;
        float b0 = boh[c], b1 = boh[c + 1];
        float2 r0 = *(float2*)(hp0 + c);
        float2 r1 = *(float2*)(hp1 + c);
        *(float2*)(hp0 + c) = make_float2(r0.x + oa[nj][0] + b0,
                                          r0.y + oa[nj][1] + b1);
        *(float2*)(hp1 + c) = make_float2(r1.x + oa[nj][2] + b0,
                                          r1.y + oa[nj][3] + b1);
    }
}

// ======================= misc kernels ======================================
template<bool DOMAX>
__device__ __forceinline__ float block_reduce(float x) {
    #pragma unroll
    for (int o = 16; o; o >>= 1) {
        float t = __shfl_xor_sync(0xFFFFFFFFu, x, o);
        x = DOMAX ? fmaxf(x, t) : x + t;
    }
    __shared__ float sh[8];
    int w = threadIdx.x >> 5;
    __syncthreads();
    if ((threadIdx.x & 31) == 0) sh[w] = x;
    __syncthreads();
    float r = sh[0];
    #pragma unroll
    for (int i = 1; i < 8; i++) r = DOMAX ? fmaxf(r, sh[i]) : r + sh[i];
    return r;
}

__global__ __launch_bounds__(256) void embed_kernel(const int* __restrict__ x,
                                                    const float* __restrict__ tok,
                                                    const float* __restrict__ pos,
                                                    float* __restrict__ H) {
    int row = blockIdx.x;
    int tid = row % TSEQ;
    size_t tb = (size_t)x[row] * DMODEL, pb = (size_t)tid * DMODEL;
    size_t hb = (size_t)row * DMODEL;
    #pragma unroll
    for (int i = 0; i < 4; i++) {
        int c = threadIdx.x + i * 256;
        H[hb + c] = tok[tb + c] + pos[pb + c];
    }
}

// layernorm: fp32 in -> fp16 out (float4 I/O)
__global__ __launch_bounds__(256) void ln_kernel(const float* __restrict__ X,
                                                 const float* __restrict__ g,
                                                 const float* __restrict__ b,
                                                 __half* __restrict__ O) {
    size_t base = (size_t)blockIdx.x * DMODEL;
    int c = threadIdx.x * 4;
    float4 v = *(const float4*)&X[base + c];
    float s = v.x + v.y + v.z + v.w;
    float sq = v.x*v.x + v.y*v.y + v.z*v.z + v.w*v.w;
    s  = block_reduce<false>(s);
    sq = block_reduce<false>(sq);
    float mu = s * (1.f / DMODEL);
    float rstd = rsqrtf(sq * (1.f / DMODEL) - mu * mu + 1e-5f);
    float4 gv = *(const float4*)&g[c];
    float4 bv = *(const float4*)&b[c];
    __half2 h0 = __floats2half2_rn((v.x - mu) * rstd * gv.x + bv.x,
                                   (v.y - mu) * rstd * gv.y + bv.y);
    __half2 h1 = __floats2half2_rn((v.z - mu) * rstd * gv.z + bv.z,
                                   (v.w - mu) * rstd * gv.w + bv.w);
    *(__half2*)&O[base + c]     = h0;
    *(__half2*)&O[base + c + 2] = h1;
}

__global__ void transpose16(const float* __restrict__ S, __half* __restrict__ D,
                            int R, int C) {
    __shared__ float t[32][33];
    int c0 = blockIdx.x * 32, r0 = blockIdx.y * 32;
    #pragma unroll
    for (int i = 0; i < 4; i++)
        t[threadIdx.y + i*8][threadIdx.x] =
            S[(size_t)(r0 + threadIdx.y + i*8) * C + c0 + threadIdx.x];
    __syncthreads();
    #pragma unroll
    for (int i = 0; i < 4; i++)
        D[(size_t)(c0 + threadIdx.y + i*8) * R + r0 + threadIdx.x] =
            __float2half(t[threadIdx.x][threadIdx.y + i*8]);
}

__global__ void repack_headT(const float* __restrict__ W, __half* __restrict__ D) {
    __shared__ float t[32][33];
    int h = blockIdx.z;
    int k0 = blockIdx.x * 32, d0 = blockIdx.y * 32;
    #pragma unroll
    for (int i = 0; i < 4; i++)
        t[threadIdx.y + i*8][threadIdx.x] =
            W[((size_t)(h*DMODEL + d0 + threadIdx.y + i*8)) * HDIM + k0 + threadIdx.x];
    __syncthreads();
    #pragma unroll
    for (int i = 0; i < 4; i++)
        D[((size_t)(h*HDIM + k0 + threadIdx.y + i*8)) * DMODEL + d0 + threadIdx.x] =
            __float2half(t[threadIdx.x][threadIdx.y + i*8]);
}

__global__ void catbias(const float* a, const float* b, const float* c, float* o) {
    int i = blockIdx.x * 256 + threadIdx.x;
    o[i] = (i < 1024) ? a[i] : (i < 2048) ? b[i - 1024] : c[i - 2048];
}

// ---------------- driver ----------------------------------------------------
extern "C" void kernel_launch(void* const* d_in, const int* in_sizes, int n_in,
                              void* d_out, int out_size) {
    const int*   x    = (const int*)  d_in[0];
    const float* tok  = (const float*)d_in[1];
    const float* pos  = (const float*)d_in[2];
    const float* Wq   = (const float*)d_in[3];
    const float* bq   = (const float*)d_in[4];
    const float* Wk   = (const float*)d_in[5];
    const float* bk   = (const float*)d_in[6];
    const float* Wv   = (const float*)d_in[7];
    const float* bv   = (const float*)d_in[8];
    const float* Wo   = (const float*)d_in[9];
    const float* bo   = (const float*)d_in[10];
    const float* W1   = (const float*)d_in[11];
    const float* b1   = (const float*)d_in[12];
    const float* W2   = (const float*)d_in[13];
    const float* b2   = (const float*)d_in[14];
    const float* ln1g = (const float*)d_in[15];
    const float* ln1b = (const float*)d_in[16];
    const float* ln2g = (const float*)d_in[17];
    const float* ln2b = (const float*)d_in[18];
    const float* lnfg = (const float*)d_in[19];
    const float* lnfb = (const float*)d_in[20];
    const float* Wout = (const float*)d_in[21];
    const float* bout = (const float*)d_in[22];
    float* out = (float*)d_out;

    float *ph, *pbqkv;
    __half *pxn, *pff, *pq, *pk, *pv, *pwqkv, *pw1t, *pw2t, *pwoT;
    cudaGetSymbolAddress((void**)&ph,    g_h);
    cudaGetSymbolAddress((void**)&pxn,   g_xn16);
    cudaGetSymbolAddress((void**)&pq,    g_q16);
    cudaGetSymbolAddress((void**)&pk,    g_k16);
    cudaGetSymbolAddress((void**)&pv,    g_v16);
    cudaGetSymbolAddress((void**)&pff,   g_ff16);
    cudaGetSymbolAddress((void**)&pwqkv, g_wqkv);
    cudaGetSymbolAddress((void**)&pbqkv, g_bqkv);
    cudaGetSymbolAddress((void**)&pw1t,  g_w1t);
    cudaGetSymbolAddress((void**)&pw2t,  g_w2t);
    cudaGetSymbolAddress((void**)&pwoT,  g_woT);

    cudaFuncSetAttribute(tgemm<0>, cudaFuncAttributeMaxDynamicSharedMemorySize, GEMM_SMEM);
    cudaFuncSetAttribute(tgemm<1>, cudaFuncAttributeMaxDynamicSharedMemorySize, GEMM_SMEM);
    cudaFuncSetAttribute(tgemm<2>, cudaFuncAttributeMaxDynamicSharedMemorySize, GEMM_SMEM);
    cudaFuncSetAttribute(tgemm<3>, cudaFuncAttributeMaxDynamicSharedMemorySize, GEMM_SMEM);

    dim3 tb(32, 8);
    repack_headT<<<dim3(2, 32, 16), tb>>>(Wq, pwqkv);
    repack_headT<<<dim3(2, 32, 16), tb>>>(Wk, pwqkv + (size_t)DMODEL*DMODEL);
    repack_headT<<<dim3(2, 32, 16), tb>>>(Wv, pwqkv + (size_t)2*DMODEL*DMODEL);
    catbias<<<12, 256>>>(bq, bk, bv, pbqkv);
    transpose16<<<dim3(FFDIM/32, DMODEL/32), tb>>>(W1, pw1t, DMODEL, FFDIM);
    transpose16<<<dim3(DMODEL/32, FFDIM/32), tb>>>(W2, pw2t, FFDIM, DMODEL);
    transpose16<<<dim3(VOCAB/32, DMODEL/32), tb>>>(Wout, pwoT, DMODEL, VOCAB);

    embed_kernel<<<NTOK, 256>>>(x, tok, pos, ph);

    for (int layer = 0; layer < NLAYER; layer++) {
        ln_kernel<<<NTOK, 256>>>(ph, ln1g, ln1b, pxn);
        tgemm<3><<<dim3(NTOK/BM, 3*DMODEL/BN), 256, GEMM_SMEM>>>(
            pxn, pwqkv, pbqkv, nullptr, pq, pk, pv, 3*DMODEL, DMODEL);

        fattn_kernel<<<dim3(TSEQ/64, BATCH*NHEAD), 128>>>(pq, pk, pv, Wo, bo, ph);

        ln_kernel<<<NTOK, 256>>>(ph, ln2g, ln2b, pxn);
        tgemm<1><<<dim3(NTOK/BM, FFDIM/BN), 256, GEMM_SMEM>>>(
            pxn, pw1t, b1, nullptr, pff, nullptr, nullptr, FFDIM, DMODEL);
        tgemm<2><<<dim3(NTOK/BM, DMODEL/BN), 256, GEMM_SMEM>>>(
            pff, pw2t, b2, ph, nullptr, nullptr, nullptr, DMODEL, FFDIM);
    }

    ln_kernel<<<NTOK, 256>>>(ph, lnfg, lnfb, pxn);
    tgemm<0><<<dim3(NTOK/BM, VOCAB/BN), 256, GEMM_SMEM>>>(
        pxn, pwoT, bout, out, nullptr, nullptr, nullptr, VOCAB, DMODEL);
}

// round 17
// speedup vs baseline: 1.0218x; 1.0019x over previous
#include <cuda_runtime.h>
#include <cuda_fp16.h>
#include <math.h>
#include <float.h>
#include <stdint.h>

// Problem constants
#define BATCH   4
#define TSEQ    1024
#define DMODEL  1024
#define NHEAD   16
#define HDIM    64
#define NLAYER  4
#define VOCAB   32000
#define NTOK    (BATCH*TSEQ)        // 4096 rows
#define FFDIM   (4*DMODEL)          // 4096

// ---------------- scratch (device globals; no allocation allowed) ----------
__device__ float  g_h   [(size_t)NTOK*DMODEL];
__device__ __half g_xn16[(size_t)NTOK*DMODEL];
__device__ __half g_q16 [(size_t)NTOK*DMODEL];
__device__ __half g_k16 [(size_t)NTOK*DMODEL];
__device__ __half g_v16 [(size_t)NTOK*DMODEL];
__device__ __half g_ff16[(size_t)NTOK*FFDIM];
__device__ __half g_wqkv[(size_t)3*DMODEL*DMODEL];   // [3072, 1024] K-major
__device__ float  g_bqkv[3*DMODEL];
__device__ __half g_w1t [(size_t)FFDIM*DMODEL];      // [4096, 1024]
__device__ __half g_w2t [(size_t)DMODEL*FFDIM];      // [1024, 4096]
__device__ __half g_woT [(size_t)VOCAB*DMODEL];      // [32000, 1024]

// ======================= PTX helpers ========================================
__device__ __forceinline__ uint32_t smem_u32(const void* p) {
    uint32_t a;
    asm("{ .reg .u64 t; cvta.to.shared.u64 t, %1; cvt.u32.u64 %0, t; }"
        : "=r"(a) : "l"(p));
    return a;
}
__device__ __forceinline__ uint32_t h2u(__half2 h) {
    union { __half2 h; uint32_t u; } cvt;
    cvt.h = h;
    return cvt.u;
}
__device__ __forceinline__ void cpa16(uint32_t dst, const void* src) {
    asm volatile("cp.async.cg.shared.global [%0], [%1], 16;" :: "r"(dst), "l"(src));
}
#define CP_COMMIT() asm volatile("cp.async.commit_group;" ::: "memory")
#define CP_WAIT(n)  asm volatile("cp.async.wait_group %0;" :: "n"(n) : "memory")

__device__ __forceinline__ void ldsm4(uint32_t* r, uint32_t a) {
    asm volatile("ldmatrix.sync.aligned.m8n8.x4.shared.b16 {%0,%1,%2,%3}, [%4];"
        : "=r"(r[0]), "=r"(r[1]), "=r"(r[2]), "=r"(r[3]) : "r"(a));
}
__device__ __forceinline__ void ldsm4t(uint32_t* r, uint32_t a) {
    asm volatile("ldmatrix.sync.aligned.m8n8.x4.trans.shared.b16 {%0,%1,%2,%3}, [%4];"
        : "=r"(r[0]), "=r"(r[1]), "=r"(r[2]), "=r"(r[3]) : "r"(a));
}
__device__ __forceinline__ void mma16816(float* c, const uint32_t* a, const uint32_t* b) {
    asm volatile("mma.sync.aligned.m16n8k16.row.col.f32.f16.f16.f32 "
        "{%0,%1,%2,%3}, {%4,%5,%6,%7}, {%8,%9}, {%0,%1,%2,%3};"
        : "+f"(c[0]), "+f"(c[1]), "+f"(c[2]), "+f"(c[3])
        : "r"(a[0]), "r"(a[1]), "r"(a[2]), "r"(a[3]), "r"(b[0]), "r"(b[1]));
}

// ======================= HMMA GEMM (128x128x32, 3-stage) ====================
// C[M,N] = A[M,K](fp16 row-major) @ B[N,K](fp16 K-major)^T + bias
// 3-stage cp.async pipeline, loads issued BEFORE compute (2 stages of cover).
// B fragments loaded pairwise via ldmatrix.x4 (half the LDSM issue count).
// MODE 0: fp32 out (Cf)   MODE 1: relu -> fp16 (Ch)
// MODE 2: fp32 += (residual into Cf)
// MODE 3: QKV split -> fp16 Ch/Chk/Chv (N-chunks of 1024)
#define BM 128
#define BN 128
#define BK 32
#define ASTR 80                       // bytes per 32-half row (64B data + 16B pad)
#define A_BYTES (BM * ASTR)           // 10240
#define STG ((BM + BN) * ASTR)        // 20480
#define GEMM_SMEM (3 * STG)           // 61440

template<int MODE>
__global__ __launch_bounds__(256)
void tgemm(const __half* __restrict__ A, const __half* __restrict__ B,
           const float* __restrict__ bias,
           float* Cf, __half* Ch, __half* Chk, __half* Chv,
           int N, int K) {
    extern __shared__ __align__(16) char dsm[];
    const int tid = threadIdx.x;
    const int w = tid >> 5, lane = tid & 31;
    const int wm = w & 1, wn = w >> 1;
    const int bm = blockIdx.x * BM, bn = blockIdx.y * BN;

    const __half* Ab = A + (size_t)bm * K;
    const __half* Bb = B + (size_t)bn * K;
    const int row_l = tid >> 2, ch_l = tid & 3;

    auto load_stage = [&](int s, int st) {
        char* bA = dsm + st * STG;
        char* bB = bA + A_BYTES;
        const __half* As = Ab + s * BK;
        const __half* Bs = Bb + s * BK;
        #pragma unroll
        for (int i = 0; i < 2; i++) {
            int r = row_l + i * 64;
            cpa16(smem_u32(bA + r * ASTR + ch_l * 16), As + (size_t)r * K + ch_l * 8);
            cpa16(smem_u32(bB + r * ASTR + ch_l * 16), Bs + (size_t)r * K + ch_l * 8);
        }
    };

    float acc[4][4][4] = {};
    const int S = K / BK;

    load_stage(0, 0); CP_COMMIT();
    load_stage(1, 1); CP_COMMIT();

    int st = 0;                       // slot of stage s
    for (int s = 0; s < S; s++) {
        if (s < S - 1) { CP_WAIT(1); } else { CP_WAIT(0); }
        __syncthreads();              // stage s ready; slot (s+2)%3 free
        if (s + 2 < S) {
            int st2 = st + 2; if (st2 >= 3) st2 -= 3;
            load_stage(s + 2, st2);
            CP_COMMIT();
        }
        uint32_t ab = smem_u32(dsm + st * STG);
        uint32_t bb = ab + A_BYTES;
        #pragma unroll
        for (int ks = 0; ks < 2; ks++) {
            uint32_t af[4][4], bf[4][2];
            #pragma unroll
            for (int mi = 0; mi < 4; mi++) {
                int r = wm * 64 + mi * 16 + (lane & 15);
                ldsm4(af[mi], ab + r * ASTR + ks * 32 + ((lane >> 4) << 4));
            }
            // B fragments pairwise: one x4 covers nj and nj+1
            #pragma unroll
            for (int njp = 0; njp < 2; njp++) {
                uint32_t r4[4];
                int r = wn * 32 + (njp * 2 + (lane >> 4)) * 8 + (lane & 7);
                ldsm4(r4, bb + r * ASTR + ks * 32 + (((lane >> 3) & 1) << 4));
                bf[njp*2][0]   = r4[0]; bf[njp*2][1]   = r4[1];
                bf[njp*2+1][0] = r4[2]; bf[njp*2+1][1] = r4[3];
            }
            #pragma unroll
            for (int mi = 0; mi < 4; mi++)
                #pragma unroll
                for (int nj = 0; nj < 4; nj++)
                    mma16816(acc[mi][nj], af[mi], bf[nj]);
        }
        if (++st == 3) st = 0;
    }

    const int l4 = lane >> 2, l2 = (lane & 3) * 2;
    #pragma unroll
    for (int mi = 0; mi < 4; mi++) {
        int m0 = bm + wm * 64 + mi * 16 + l4;
        #pragma unroll
        for (int nj = 0; nj < 4; nj++) {
            int ng = bn + wn * 32 + nj * 8 + l2;
            float b0 = bias[ng], b1 = bias[ng + 1];
            float v00 = acc[mi][nj][0] + b0, v01 = acc[mi][nj][1] + b1;
            float v10 = acc[mi][nj][2] + b0, v11 = acc[mi][nj][3] + b1;
            if (MODE == 3) {
                int which = bn >> 10;
                __half* dst = (which == 0) ? Ch : (which == 1) ? Chk : Chv;
                int nc = ng & 1023;
                *(__half2*)(dst + (size_t)m0 * DMODEL + nc)       = __floats2half2_rn(v00, v01);
                *(__half2*)(dst + (size_t)(m0 + 8) * DMODEL + nc) = __floats2half2_rn(v10, v11);
            } else if (MODE == 1) {
                *(__half2*)(Ch + (size_t)m0 * N + ng) =
                    __floats2half2_rn(fmaxf(v00, 0.f), fmaxf(v01, 0.f));
                *(__half2*)(Ch + (size_t)(m0 + 8) * N + ng) =
                    __floats2half2_rn(fmaxf(v10, 0.f), fmaxf(v11, 0.f));
            } else {
                float* p0 = Cf + (size_t)m0 * N + ng;
                float* p1 = Cf + (size_t)(m0 + 8) * N + ng;
                if (MODE == 2) {
                    float2 o0 = *(float2*)p0, o1 = *(float2*)p1;
                    v00 += o0.x; v01 += o0.y; v10 += o1.x; v11 += o1.y;
                }
                *(float2*)p0 = make_float2(v00, v01);
                *(float2*)p1 = make_float2(v10, v11);
            }
        }
    }
}

// ======================= fused flash attention + O projection ==============
// (64 Q-rows/block, 128 threads.) Double-buffered cp.async K/V prefetch.
// K fragments AND V fragments loaded pairwise via ldmatrix.x4 / x4.trans.
// Exact source-quirk mask: scale, then (s>t || val==0) -> -inf. Online
// softmax in fp32. Epilogue: O_norm (fp16 A-frags) @ Wo[h] (fp16 in reused
// sQ smem, x4.trans pairwise), + bias, += into H.
#define FSTR 144   // 64 halves (128B) + 16B pad per row

__global__ __launch_bounds__(128)
void fattn_kernel(const __half* __restrict__ Q, const __half* __restrict__ K,
                  const __half* __restrict__ V,
                  const float* __restrict__ Wo, const float* __restrict__ bo,
                  float* __restrict__ H) {
    __shared__ __align__(16) char sQ[64 * FSTR];
    __shared__ __align__(16) char sK[2][64 * FSTR];
    __shared__ __align__(16) char sV[2][64 * FSTR];
    const int t0 = blockIdx.x * 64;
    const int bh = blockIdx.y, b = bh >> 4, h = bh & 15;
    const int tid = threadIdx.x, w = tid >> 5, lane = tid & 31;
    const int l4 = lane >> 2, l2 = (lane & 3) * 2;
    const size_t base = (size_t)b * TSEQ * DMODEL + h * HDIM;

    // load Q tile (64 x 64 halfs), direct stores
    #pragma unroll
    for (int i = 0; i < 4; i++) {
        int idx = tid + i * 128;
        int r = idx >> 3, cseg = idx & 7;
        *(uint4*)(sQ + r * FSTR + cseg * 16) =
            *(const uint4*)(Q + base + (size_t)(t0 + r) * DMODEL + cseg * 8);
    }

    auto load_kv = [&](int s0, int buf) {
        #pragma unroll
        for (int i = 0; i < 4; i++) {
            int idx = tid + i * 128;
            int r = idx >> 3, cseg = idx & 7;
            cpa16(smem_u32(&sK[buf][r * FSTR + cseg * 16]),
                  K + base + (size_t)(s0 + r) * DMODEL + cseg * 8);
            cpa16(smem_u32(&sV[buf][r * FSTR + cseg * 16]),
                  V + base + (size_t)(s0 + r) * DMODEL + cseg * 8);
        }
    };

    // prefetch KV block 0
    load_kv(0, 0);
    CP_COMMIT();
    __syncthreads();            // sQ visible to all

    uint32_t sqb = smem_u32(sQ);
    uint32_t qf[4][4];
    #pragma unroll
    for (int ks = 0; ks < 4; ks++)
        ldsm4(qf[ks], sqb + (w * 16 + (lane & 15)) * FSTR + ks * 32
                       + ((lane >> 4) << 4));
    __syncthreads();            // all warps done reading sQ

    // repurpose sQ: Wo[h] as fp16 [v][n] 64x64 (row stride FSTR)
    {
        const float* woh = Wo + (size_t)h * (HDIM * HDIM);
        #pragma unroll
        for (int i = 0; i < 8; i++) {
            int idx = tid + i * 128;               // 0..1023
            int r = idx >> 4, c4 = (idx & 15) * 4;
            float4 v = *(const float4*)(woh + r * HDIM + c4);
            *(__half2*)(sQ + r * FSTR + c4 * 2)     = __floats2half2_rn(v.x, v.y);
            *(__half2*)(sQ + r * FSTR + c4 * 2 + 4) = __floats2half2_rn(v.z, v.w);
        }
    }

    float m_run[2] = {-FLT_MAX, -FLT_MAX};
    float l_run[2] = {0.f, 0.f};
    float o[8][4] = {};
    const int tg0 = t0 + w * 16 + l4;      // rows (within batch) this thread owns
    const int tg1 = tg0 + 8;
    const int nblk = t0 / 64 + 1;

    for (int ib = 0; ib < nblk; ib++) {
        const int s0 = ib * 64;
        const int buf = ib & 1;
        if (ib + 1 < nblk) load_kv(s0 + 64, buf ^ 1);
        CP_COMMIT();
        if (ib + 1 < nblk) { CP_WAIT(1); } else { CP_WAIT(0); }
        __syncthreads();        // KV[buf] (and, on iter 0, sQ=Wo) visible

        uint32_t skb = smem_u32(&sK[buf][0]);
        uint32_t svb = smem_u32(&sV[buf][0]);

        // ---- S = Q K^T (fp32 accum), K fragments pairwise via x4 ----
        float sc[8][4] = {};
        #pragma unroll
        for (int ks = 0; ks < 4; ks++) {
            uint32_t bfk[8][2];
            #pragma unroll
            for (int njp = 0; njp < 4; njp++) {
                uint32_t r4[4];
                int r = (njp * 2 + (lane >> 4)) * 8 + (lane & 7);
                ldsm4(r4, skb + r * FSTR + ks * 32 + (((lane >> 3) & 1) << 4));
                bfk[njp*2][0]   = r4[0]; bfk[njp*2][1]   = r4[1];
                bfk[njp*2+1][0] = r4[2]; bfk[njp*2+1][1] = r4[3];
            }
            #pragma unroll
            for (int nj = 0; nj < 8; nj++)
                mma16816(sc[nj], qf[ks], bfk[nj]);
        }
        // ---- scale + mask (source quirk) ----
        float rmax0 = -FLT_MAX, rmax1 = -FLT_MAX;
        #pragma unroll
        for (int nj = 0; nj < 8; nj++) {
            int sg = s0 + nj * 8 + l2;
            #pragma unroll
            for (int q = 0; q < 2; q++) {
                float v0 = sc[nj][q] * 0.125f;
                float v2 = sc[nj][q + 2] * 0.125f;
                if (sg + q > tg0 || v0 == 0.f) v0 = -FLT_MAX;
                if (sg + q > tg1 || v2 == 0.f) v2 = -FLT_MAX;
                sc[nj][q] = v0; sc[nj][q + 2] = v2;
                rmax0 = fmaxf(rmax0, v0); rmax1 = fmaxf(rmax1, v2);
            }
        }
        rmax0 = fmaxf(rmax0, __shfl_xor_sync(0xFFFFFFFFu, rmax0, 1));
        rmax0 = fmaxf(rmax0, __shfl_xor_sync(0xFFFFFFFFu, rmax0, 2));
        rmax1 = fmaxf(rmax1, __shfl_xor_sync(0xFFFFFFFFu, rmax1, 1));
        rmax1 = fmaxf(rmax1, __shfl_xor_sync(0xFFFFFFFFu, rmax1, 2));
        float nm0 = fmaxf(m_run[0], rmax0), nm1 = fmaxf(m_run[1], rmax1);
        float al0 = __expf(m_run[0] - nm0), al1 = __expf(m_run[1] - nm1);
        m_run[0] = nm0; m_run[1] = nm1;
        float rs0 = 0.f, rs1 = 0.f;
        #pragma unroll
        for (int nj = 0; nj < 8; nj++) {
            #pragma unroll
            for (int q = 0; q < 2; q++) {
                float p0 = (sc[nj][q]     == -FLT_MAX) ? 0.f : __expf(sc[nj][q]     - nm0);
                float p2 = (sc[nj][q + 2] == -FLT_MAX) ? 0.f : __expf(sc[nj][q + 2] - nm1);
                sc[nj][q] = p0; sc[nj][q + 2] = p2;
                rs0 += p0; rs1 += p2;
            }
        }
        rs0 += __shfl_xor_sync(0xFFFFFFFFu, rs0, 1);
        rs0 += __shfl_xor_sync(0xFFFFFFFFu, rs0, 2);
        rs1 += __shfl_xor_sync(0xFFFFFFFFu, rs1, 1);
        rs1 += __shfl_xor_sync(0xFFFFFFFFu, rs1, 2);
        l_run[0] = l_run[0] * al0 + rs0;
        l_run[1] = l_run[1] * al1 + rs1;
        #pragma unroll
        for (int nj = 0; nj < 8; nj++) {
            o[nj][0] *= al0; o[nj][1] *= al0;
            o[nj][2] *= al1; o[nj][3] *= al1;
        }
        // ---- O += P V  (V fragments pairwise via x4.trans) ----
        #pragma unroll
        for (int kv = 0; kv < 4; kv++) {
            uint32_t pa[4];
            pa[0] = h2u(__floats2half2_rn(sc[2*kv][0],   sc[2*kv][1]));
            pa[1] = h2u(__floats2half2_rn(sc[2*kv][2],   sc[2*kv][3]));
            pa[2] = h2u(__floats2half2_rn(sc[2*kv+1][0], sc[2*kv+1][1]));
            pa[3] = h2u(__floats2half2_rn(sc[2*kv+1][2], sc[2*kv+1][3]));
            uint32_t bfv[8][2];
            #pragma unroll
            for (int njp = 0; njp < 4; njp++) {
                uint32_t r4[4];
                ldsm4t(r4, svb + (kv * 16 + (lane & 15)) * FSTR
                             + njp * 32 + ((lane >> 4) << 4));
                bfv[njp*2][0]   = r4[0]; bfv[njp*2][1]   = r4[1];
                bfv[njp*2+1][0] = r4[2]; bfv[njp*2+1][1] = r4[3];
            }
            #pragma unroll
            for (int nj = 0; nj < 8; nj++)
                mma16816(o[nj], pa, bfv[nj]);
        }
        __syncthreads();        // protect KV[buf] before next prefetch reuses it
    }

    // ---- fused O projection: (O * inv_l) @ Wo[h] + bo[h], += into H ----
    float inv0 = 1.f / l_run[0], inv1 = 1.f / l_run[1];
    float oa[8][4] = {};
    uint32_t swo = smem_u32(sQ);
    #pragma unroll
    for (int kv = 0; kv < 4; kv++) {
        uint32_t pa[4];
        pa[0] = h2u(__floats2half2_rn(o[2*kv][0]   * inv0, o[2*kv][1]   * inv0));
        pa[1] = h2u(__floats2half2_rn(o[2*kv][2]   * inv1, o[2*kv][3]   * inv1));
        pa[2] = h2u(__floats2half2_rn(o[2*kv+1][0] * inv0, o[2*kv+1][1] * inv0));
        pa[3] = h2u(__floats2half2_rn(o[2*kv+1][2] * inv1, o[2*kv+1][3] * inv1));
        uint32_t bfw[8][2];
        #pragma unroll
        for (int njp = 0; njp < 4; njp++) {
            uint32_t r4[4];
            ldsm4t(r4, swo + (kv * 16 + (lane & 15)) * FSTR
                         + njp * 32 + ((lane >> 4) << 4));
            bfw[njp*2][0]   = r4[0]; bfw[njp*2][1]   = r4[1];
            bfw[njp*2+1][0] = r4[2]; bfw[njp*2+1][1] = r4[3];
        }
        #pragma unroll
        for (int nj = 0; nj < 8; nj++)
            mma16816(oa[nj], pa, bfw[nj]);
    }
    const float* boh = bo + h * HDIM;
    float* hp0 = H + (size_t)(b * TSEQ + tg0) * DMODEL + h * HDIM;
    float* hp1 = H + (size_t)(b * TSEQ + tg1) * DMODEL + h * HDIM;
    #pragma unroll
    for (int nj = 0; nj < 8; nj++) {
        int c = nj * 8 + l2;
        float b0 = boh[c], b1 = boh[c + 1];
        float2 r0 = *(float2*)(hp0 + c);
        float2 r1 = *(float2*)(hp1 + c);
        *(float2*)(hp0 + c) = make_float2(r0.x + oa[nj][0] + b0,
                                          r0.y + oa[nj][1] + b1);
        *(float2*)(hp1 + c) = make_float2(r1.x + oa[nj][2] + b0,
                                          r1.y + oa[nj][3] + b1);
    }
}

// ======================= misc kernels ======================================
template<bool DOMAX>
__device__ __forceinline__ float block_reduce(float x) {
    #pragma unroll
    for (int o = 16; o; o >>= 1) {
        float t = __shfl_xor_sync(0xFFFFFFFFu, x, o);
        x = DOMAX ? fmaxf(x, t) : x + t;
    }
    __shared__ float sh[8];
    int w = threadIdx.x >> 5;
    __syncthreads();
    if ((threadIdx.x & 31) == 0) sh[w] = x;
    __syncthreads();
    float r = sh[0];
    #pragma unroll
    for (int i = 1; i < 8; i++) r = DOMAX ? fmaxf(r, sh[i]) : r + sh[i];
    return r;
}

__global__ __launch_bounds__(256) void embed_kernel(const int* __restrict__ x,
                                                    const float* __restrict__ tok,
                                                    const float* __restrict__ pos,
                                                    float* __restrict__ H) {
    int row = blockIdx.x;
    int tid = row % TSEQ;
    size_t tb = (size_t)x[row] * DMODEL, pb = (size_t)tid * DMODEL;
    size_t hb = (size_t)row * DMODEL;
    #pragma unroll
    for (int i = 0; i < 4; i++) {
        int c = threadIdx.x + i * 256;
        H[hb + c] = tok[tb + c] + pos[pb + c];
    }
}

// layernorm: fp32 in -> fp16 out (float4 I/O)
__global__ __launch_bounds__(256) void ln_kernel(const float* __restrict__ X,
                                                 const float* __restrict__ g,
                                                 const float* __restrict__ b,
                                                 __half* __restrict__ O) {
    size_t base = (size_t)blockIdx.x * DMODEL;
    int c = threadIdx.x * 4;
    float4 v = *(const float4*)&X[base + c];
    float s = v.x + v.y + v.z + v.w;
    float sq = v.x*v.x + v.y*v.y + v.z*v.z + v.w*v.w;
    s  = block_reduce<false>(s);
    sq = block_reduce<false>(sq);
    float mu = s * (1.f / DMODEL);
    float rstd = rsqrtf(sq * (1.f / DMODEL) - mu * mu + 1e-5f);
    float4 gv = *(const float4*)&g[c];
    float4 bv = *(const float4*)&b[c];
    __half2 h0 = __floats2half2_rn((v.x - mu) * rstd * gv.x + bv.x,
                                   (v.y - mu) * rstd * gv.y + bv.y);
    __half2 h1 = __floats2half2_rn((v.z - mu) * rstd * gv.z + bv.z,
                                   (v.w - mu) * rstd * gv.w + bv.w);
    *(__half2*)&O[base + c]     = h0;
    *(__half2*)&O[base + c + 2] = h1;
}

__global__ void transpose16(const float* __restrict__ S, __half* __restrict__ D,
                            int R, int C) {
    __shared__ float t[32][33];
    int c0 = blockIdx.x * 32, r0 = blockIdx.y * 32;
    #pragma unroll
    for (int i = 0; i < 4; i++)
        t[threadIdx.y + i*8][threadIdx.x] =
            S[(size_t)(r0 + threadIdx.y + i*8) * C + c0 + threadIdx.x];
    __syncthreads();
    #pragma unroll
    for (int i = 0; i < 4; i++)
        D[(size_t)(c0 + threadIdx.y + i*8) * R + r0 + threadIdx.x] =
            __float2half(t[threadIdx.x][threadIdx.y + i*8]);
}

__global__ void repack_headT(const float* __restrict__ W, __half* __restrict__ D) {
    __shared__ float t[32][33];
    int h = blockIdx.z;
    int k0 = blockIdx.x * 32, d0 = blockIdx.y * 32;
    #pragma unroll
    for (int i = 0; i < 4; i++)
        t[threadIdx.y + i*8][threadIdx.x] =
            W[((size_t)(h*DMODEL + d0 + threadIdx.y + i*8)) * HDIM + k0 + threadIdx.x];
    __syncthreads();
    #pragma unroll
    for (int i = 0; i < 4; i++)
        D[((size_t)(h*HDIM + k0 + threadIdx.y + i*8)) * DMODEL + d0 + threadIdx.x] =
            __float2half(t[threadIdx.x][threadIdx.y + i*8]);
}

__global__ void catbias(const float* a, const float* b, const float* c, float* o) {
    int i = blockIdx.x * 256 + threadIdx.x;
    o[i] = (i < 1024) ? a[i] : (i < 2048) ? b[i - 1024] : c[i - 2048];
}

// ---------------- driver ----------------------------------------------------
extern "C" void kernel_launch(void* const* d_in, const int* in_sizes, int n_in,
                              void* d_out, int out_size) {
    const int*   x    = (const int*)  d_in[0];
    const float* tok  = (const float*)d_in[1];
    const float* pos  = (const float*)d_in[2];
    const float* Wq   = (const float*)d_in[3];
    const float* bq   = (const float*)d_in[4];
    const float* Wk   = (const float*)d_in[5];
    const float* bk   = (const float*)d_in[6];
    const float* Wv   = (const float*)d_in[7];
    const float* bv   = (const float*)d_in[8];
    const float* Wo   = (const float*)d_in[9];
    const float* bo   = (const float*)d_in[10];
    const float* W1   = (const float*)d_in[11];
    const float* b1   = (const float*)d_in[12];
    const float* W2   = (const float*)d_in[13];
    const float* b2   = (const float*)d_in[14];
    const float* ln1g = (const float*)d_in[15];
    const float* ln1b = (const float*)d_in[16];
    const float* ln2g = (const float*)d_in[17];
    const float* ln2b = (const float*)d_in[18];
    const float* lnfg = (const float*)d_in[19];
    const float* lnfb = (const float*)d_in[20];
    const float* Wout = (const float*)d_in[21];
    const float* bout = (const float*)d_in[22];
    float* out = (float*)d_out;

    float *ph, *pbqkv;
    __half *pxn, *pff, *pq, *pk, *pv, *pwqkv, *pw1t, *pw2t, *pwoT;
    cudaGetSymbolAddress((void**)&ph,    g_h);
    cudaGetSymbolAddress((void**)&pxn,   g_xn16);
    cudaGetSymbolAddress((void**)&pq,    g_q16);
    cudaGetSymbolAddress((void**)&pk,    g_k16);
    cudaGetSymbolAddress((void**)&pv,    g_v16);
    cudaGetSymbolAddress((void**)&pff,   g_ff16);
    cudaGetSymbolAddress((void**)&pwqkv, g_wqkv);
    cudaGetSymbolAddress((void**)&pbqkv, g_bqkv);
    cudaGetSymbolAddress((void**)&pw1t,  g_w1t);
    cudaGetSymbolAddress((void**)&pw2t,  g_w2t);
    cudaGetSymbolAddress((void**)&pwoT,  g_woT);

    cudaFuncSetAttribute(tgemm<0>, cudaFuncAttributeMaxDynamicSharedMemorySize, GEMM_SMEM);
    cudaFuncSetAttribute(tgemm<1>, cudaFuncAttributeMaxDynamicSharedMemorySize, GEMM_SMEM);
    cudaFuncSetAttribute(tgemm<2>, cudaFuncAttributeMaxDynamicSharedMemorySize, GEMM_SMEM);
    cudaFuncSetAttribute(tgemm<3>, cudaFuncAttributeMaxDynamicSharedMemorySize, GEMM_SMEM);

    dim3 tb(32, 8);
    repack_headT<<<dim3(2, 32, 16), tb>>>(Wq, pwqkv);
    repack_headT<<<dim3(2, 32, 16), tb>>>(Wk, pwqkv + (size_t)DMODEL*DMODEL);
    repack_headT<<<dim3(2, 32, 16), tb>>>(Wv, pwqkv + (size_t)2*DMODEL*DMODEL);
    catbias<<<12, 256>>>(bq, bk, bv, pbqkv);
    transpose16<<<dim3(FFDIM/32, DMODEL/32), tb>>>(W1, pw1t, DMODEL, FFDIM);
    transpose16<<<dim3(DMODEL/32, FFDIM/32), tb>>>(W2, pw2t, FFDIM, DMODEL);
    transpose16<<<dim3(VOCAB/32, DMODEL/32), tb>>>(Wout, pwoT, DMODEL, VOCAB);

    embed_kernel<<<NTOK, 256>>>(x, tok, pos, ph);

    for (int layer = 0; layer < NLAYER; layer++) {
        ln_kernel<<<NTOK, 256>>>(ph, ln1g, ln1b, pxn);
        tgemm<3><<<dim3(NTOK/BM, 3*DMODEL/BN), 256, GEMM_SMEM>>>(
            pxn, pwqkv, pbqkv, nullptr, pq, pk, pv, 3*DMODEL, DMODEL);

        fattn_kernel<<<dim3(TSEQ/64, BATCH*NHEAD), 128>>>(pq, pk, pv, Wo, bo, ph);

        ln_kernel<<<NTOK, 256>>>(ph, ln2g, ln2b, pxn);
        tgemm<1><<<dim3(NTOK/BM, FFDIM/BN), 256, GEMM_SMEM>>>(
            pxn, pw1t, b1, nullptr, pff, nullptr, nullptr, FFDIM, DMODEL);
        tgemm<2><<<dim3(NTOK/BM, DMODEL/BN), 256, GEMM_SMEM>>>(
            pff, pw2t, b2, ph, nullptr, nullptr, nullptr, DMODEL, FFDIM);
    }

    ln_kernel<<<NTOK, 256>>>(ph, lnfg, lnfb, pxn);
    tgemm<0><<<dim3(NTOK/BM, VOCAB/BN), 256, GEMM_SMEM>>>(
        pxn, pwoT, bout, out, nullptr, nullptr, nullptr, VOCAB, DMODEL);
}